// round 8
// baseline (speedup 1.0000x reference)
#include <cuda_runtime.h>
#include <cuda_bf16.h>

#define Hh 96
#define Ww 96
#define HW 9216
#define Cc 64
#define Oo 64
#define Bb 4
#define NT 9            // taps per frame
#define ON 576          // Oo*NT
#define NBX 36          // kB blocks per (b,o) image

// Scratch: Y[(o*9+n)*B + b][p]  (85 MB)
__device__ float g_Y[(size_t)ON * Bb * HW];
__device__ float g_scale[Oo];
__device__ float g_shift[Oo];
__device__ float g_psum[Oo * Bb * NBX];
__device__ float g_psq [Oo * Bb * NBX];

__device__ __forceinline__ unsigned long long pack2(float lo, float hi) {
    unsigned long long r;
    asm("mov.b64 %0, {%1, %2};" : "=l"(r) : "f"(lo), "f"(hi));
    return r;
}
__device__ __forceinline__ void unpack2(unsigned long long v, float &lo, float &hi) {
    asm("mov.b64 {%0, %1}, %2;" : "=f"(lo), "=f"(hi) : "l"(v));
}
__device__ __forceinline__ void fma2(unsigned long long &d, unsigned long long a, unsigned long long b) {
    asm("fma.rn.f32x2 %0, %1, %2, %0;" : "+l"(d) : "l"(a), "l"(b));
}

// ---------------------------------------------------------------------------
// Kernel A: Y[o,n,b,p] = sum_c w[o,c,n] * x[b,c,p]
// Packed f32x2: each thread carries 2 pixels (p0, p0+256) per 64-bit lane pair.
// Weights duplicated (w,w) in smem [c][j] u64; warp-uniform LDS.128 reads 2 j's.
// Per c-iter per warp: 2 LDG + 18 broadcast LDS.128 + 36 FMA2  (was 72 FFMA).
// Grid: (HW/512=18, B=4, O/4=16), 256 threads.
// ---------------------------------------------------------------------------
__global__ __launch_bounds__(256) void kA(const float* __restrict__ x,
                                          const float* __restrict__ cw) {
    __shared__ alignas(16) unsigned long long wsm[64 * 36];  // [c][j], row 288B

    const int b  = blockIdx.y;
    const int o0 = blockIdx.z * 4;

    for (int idx = threadIdx.x; idx < 36 * 64; idx += 256) {
        int j = idx >> 6, c = idx & 63;
        int oo = j / 9, n = j - oo * 9;
        float v = cw[(size_t)(o0 + oo) * (Cc * NT) + c * NT + n];
        wsm[c * 36 + j] = pack2(v, v);
    }
    __syncthreads();

    const int p0 = blockIdx.x * 512 + threadIdx.x;   // second pixel = p0+256
    const float* xb = x + (size_t)b * Cc * HW;

    unsigned long long acc[36];
#pragma unroll
    for (int j = 0; j < 36; j++) acc[j] = 0ull;

#pragma unroll 2
    for (int c = 0; c < Cc; c++) {
        unsigned long long a = pack2(xb[c * HW + p0], xb[c * HW + p0 + 256]);
        const ulonglong2* wrow = reinterpret_cast<const ulonglong2*>(&wsm[c * 36]);
#pragma unroll
        for (int q = 0; q < 18; q++) {
            ulonglong2 w2 = wrow[q];
            fma2(acc[2 * q],     a, w2.x);
            fma2(acc[2 * q + 1], a, w2.y);
        }
    }

#pragma unroll
    for (int j = 0; j < 36; j++) {
        int oo = j / 9, n = j - oo * 9;
        float lo, hi;
        unpack2(acc[j], lo, hi);
        float* Yp = g_Y + (size_t)(((o0 + oo) * NT + n) * Bb + b) * HW;
        Yp[p0]       = lo;
        Yp[p0 + 256] = hi;
    }
}

// ---------------------------------------------------------------------------
// Kernel B: pre-BN output = bias[o] + sum_n bilinear-blend(Y[o,n,b]),
// plus deterministic per-block BN partial sums.
// Grid: (HW/256=36, B=4, O=64)
// ---------------------------------------------------------------------------
struct alignas(16) Tap { int lo; int hi; float wl; float wr; };

__global__ __launch_bounds__(256) void kB(const float* __restrict__ frames,
                                          const float* __restrict__ bias,
                                          float* __restrict__ out) {
    __shared__ Tap SX[NT][Ww];
    __shared__ Tap SY[NT][Hh];
    __shared__ float rs[256], rq[256];

    const int o = blockIdx.z;
    const int b = blockIdx.y;

    // Precompute taps. idx < 864: x-direction; idx >= 864: y-direction.
    for (int idx = threadIdx.x; idx < 2 * NT * 96; idx += 256) {
        int which = (idx >= NT * 96) ? 1 : 0;
        int r = idx - which * (NT * 96);
        int n = r / 96, t = r - n * 96;
        float d  = frames[o * (2 * NT) + which * NT + n]; // first 9: x-offs, last 9: y-offs
        float pf = d + (float)t;                          // matches ref: frame + coord in f32
        float ff = floorf(pf);
        float lof = fminf(fmaxf(ff, 0.f), 95.f);
        float hif = fminf(fmaxf(ff + 1.f, 0.f), 95.f);
        float pc  = fminf(fmaxf(pf, 0.f), 95.f);
        Tap tp;
        tp.lo = (int)lof;
        tp.hi = (int)hif;
        tp.wl = 1.f + lof - pc;   // (1 + (lt - pc))
        tp.wr = 1.f - hif + pc;   // (1 - (rb - pc))
        if (which == 0) SX[n][t] = tp; else SY[n][t] = tp;
    }
    __syncthreads();

    const int p = blockIdx.x * 256 + threadIdx.x;
    const int h = p / Ww, w = p - h * Ww;
    const float* Ybase = g_Y + (size_t)(o * NT * Bb + b) * HW;

    float acc = 0.f;
#pragma unroll
    for (int n = 0; n < NT; n++) {
        Tap tx = SX[n][w];
        Tap ty = SY[n][h];
        const float* Yp = Ybase + (size_t)n * (Bb * HW);
        const float* rT = Yp + ty.lo * Ww;
        const float* rB = Yp + ty.hi * Ww;
        float vT = tx.wl * rT[tx.lo] + tx.wr * rT[tx.hi];
        float vB = tx.wl * rB[tx.lo] + tx.wr * rB[tx.hi];
        acc += ty.wl * vT + ty.wr * vB;
    }
    float v = acc + bias[o];
    out[(size_t)(b * Oo + o) * HW + p] = v;

    // Deterministic BN partials for this block
    rs[threadIdx.x] = v;
    rq[threadIdx.x] = v * v;
    __syncthreads();
    for (int st = 128; st > 0; st >>= 1) {
        if (threadIdx.x < st) {
            rs[threadIdx.x] += rs[threadIdx.x + st];
            rq[threadIdx.x] += rq[threadIdx.x + st];
        }
        __syncthreads();
    }
    if (threadIdx.x == 0) {
        int slot = (o * Bb + b) * NBX + blockIdx.x;
        g_psum[slot] = rs[0];
        g_psq [slot] = rq[0];
    }
}

// ---------------------------------------------------------------------------
// Kernel C1: reduce 144 partials per channel -> scale/shift. Grid: 64 blocks.
// ---------------------------------------------------------------------------
__global__ __launch_bounds__(256) void kC1(const float* __restrict__ gamma,
                                           const float* __restrict__ beta) {
    const int o = blockIdx.x;
    const int P = Bb * NBX;   // 144
    float s = 0.f, s2 = 0.f;
    if (threadIdx.x < P) {
        s  = g_psum[o * P + threadIdx.x];
        s2 = g_psq [o * P + threadIdx.x];
    }
    __shared__ float rs[256], rq[256];
    rs[threadIdx.x] = s;
    rq[threadIdx.x] = s2;
    __syncthreads();
    for (int st = 128; st > 0; st >>= 1) {
        if (threadIdx.x < st) {
            rs[threadIdx.x] += rs[threadIdx.x + st];
            rq[threadIdx.x] += rq[threadIdx.x + st];
        }
        __syncthreads();
    }
    if (threadIdx.x == 0) {
        const float inv = 1.f / (float)(Bb * HW);
        float mean = rs[0] * inv;
        float var  = rq[0] * inv - mean * mean;
        float rstd = rsqrtf(var + 1e-5f);
        float sc = gamma[o] * rstd;
        g_scale[o] = sc;
        g_shift[o] = beta[o] - mean * sc;
    }
}

// ---------------------------------------------------------------------------
// Kernel C2: in-place normalize + ReLU, float4. Grid: 2304 blocks of 256.
// ---------------------------------------------------------------------------
__global__ __launch_bounds__(256) void kC2(float4* __restrict__ out) {
    const int idx = blockIdx.x * 256 + threadIdx.x;       // float4 index
    const int o = (idx / (HW / 4)) & 63;
    float sc = g_scale[o], sh = g_shift[o];
    float4 v = out[idx];
    v.x = fmaxf(fmaf(v.x, sc, sh), 0.f);
    v.y = fmaxf(fmaf(v.y, sc, sh), 0.f);
    v.z = fmaxf(fmaf(v.z, sc, sh), 0.f);
    v.w = fmaxf(fmaf(v.w, sc, sh), 0.f);
    out[idx] = v;
}

extern "C" void kernel_launch(void* const* d_in, const int* in_sizes, int n_in,
                              void* d_out, int out_size) {
    const float* x      = (const float*)d_in[0];
    const float* frames = (const float*)d_in[1];
    const float* cw     = (const float*)d_in[2];
    const float* cb     = (const float*)d_in[3];
    const float* gamma  = (const float*)d_in[4];
    const float* beta   = (const float*)d_in[5];
    float* out = (float*)d_out;

    kA<<<dim3(HW / 512, Bb, Oo / 4), 256>>>(x, cw);
    kB<<<dim3(HW / 256, Bb, Oo), 256>>>(frames, cb, out);
    kC1<<<Oo, 256>>>(gamma, beta);
    kC2<<<(Bb * Oo * HW) / 1024, 256>>>((float4*)out);
}

// round 11
// speedup vs baseline: 1.3701x; 1.3701x over previous
#include <cuda_runtime.h>
#include <cuda_bf16.h>
#include <mma.h>
#include <cstdint>

using namespace nvcuda;

#define Hh 96
#define Ww 96
#define HW 9216
#define Cc 64
#define Oo 64
#define Bb 4
#define NT 9            // taps per frame
#define ON 576          // Oo*NT = valid GEMM rows
#define MPAD 640        // padded to 5 tiles of 128
#define NBX 36          // kB blocks per (b,o) image
#define KPAD 200        // smem row stride in bf16 (192 used + 8 pad; 400B breaks LDSM conflicts)

// Scratch
__device__ float g_Y[(size_t)ON * Bb * HW];                          // 85 MB
__device__ __align__(16) __nv_bfloat16 g_whi[MPAD * Cc];             // W split hi
__device__ __align__(16) __nv_bfloat16 g_wlo[MPAD * Cc];             // W split lo
__device__ __align__(16) __nv_bfloat16 g_xhi[(size_t)Bb * HW * Cc];  // xT split hi (K-major rows)
__device__ __align__(16) __nv_bfloat16 g_xlo[(size_t)Bb * HW * Cc];  // xT split lo
__device__ float g_scale[Oo];
__device__ float g_shift[Oo];
__device__ float g_psum[Oo * Bb * NBX];
__device__ float g_psq [Oo * Bb * NBX];

// ---------------------------------------------------------------------------
// kPW: split conv weights into bf16 hi/lo, layout Wpad[j][c], j = o*9+n, pad 0.
// ---------------------------------------------------------------------------
__global__ __launch_bounds__(256) void kPW(const float* __restrict__ cw) {
    int idx = blockIdx.x * 256 + threadIdx.x;      // < MPAD*64
    if (idx >= MPAD * Cc) return;
    int j = idx >> 6, c = idx & 63;
    float v = 0.f;
    if (j < ON) {
        int o = j / 9, n = j - o * 9;
        v = cw[(size_t)o * (Cc * NT) + c * NT + n];
    }
    __nv_bfloat16 hi = __float2bfloat16(v);
    __nv_bfloat16 lo = __float2bfloat16(v - __bfloat162float(hi));
    g_whi[idx] = hi;
    g_wlo[idx] = lo;
}

// ---------------------------------------------------------------------------
// kPX: transpose+split x -> xT[g][c] (g = b*HW+p), 128B K-major rows.
// ---------------------------------------------------------------------------
__global__ __launch_bounds__(256) void kPX(const float* __restrict__ x) {
    int g = blockIdx.x * 256 + threadIdx.x;        // < Bb*HW
    int b = g / HW, p = g - b * HW;
    const float* xp = x + (size_t)b * Cc * HW + p;
    uint32_t hibuf[32], lobuf[32];
#pragma unroll
    for (int c2 = 0; c2 < 32; c2++) {
        float v0 = xp[(2 * c2) * HW];
        float v1 = xp[(2 * c2 + 1) * HW];
        __nv_bfloat16 h0 = __float2bfloat16(v0);
        __nv_bfloat16 h1 = __float2bfloat16(v1);
        __nv_bfloat16 l0 = __float2bfloat16(v0 - __bfloat162float(h0));
        __nv_bfloat16 l1 = __float2bfloat16(v1 - __bfloat162float(h1));
        __nv_bfloat162 hp = __halves2bfloat162(h0, h1);
        __nv_bfloat162 lp = __halves2bfloat162(l0, l1);
        hibuf[c2] = *reinterpret_cast<uint32_t*>(&hp);
        lobuf[c2] = *reinterpret_cast<uint32_t*>(&lp);
    }
    uint4* dh = reinterpret_cast<uint4*>(g_xhi + (size_t)g * Cc);
    uint4* dl = reinterpret_cast<uint4*>(g_xlo + (size_t)g * Cc);
#pragma unroll
    for (int q = 0; q < 8; q++) {
        dh[q] = make_uint4(hibuf[4*q], hibuf[4*q+1], hibuf[4*q+2], hibuf[4*q+3]);
        dl[q] = make_uint4(lobuf[4*q], lobuf[4*q+1], lobuf[4*q+2], lobuf[4*q+3]);
    }
}

// ---------------------------------------------------------------------------
// kG: WMMA bf16 split GEMM (legacy sm_80 tensor path; valid on target sm_100).
// D[128,128] = A''[128,192] x B''[192,128], where along K:
//   A'' = [Whi | Whi | Wlo],  B''(col-major) rows n = [Xhi | Xlo | Xhi]
// giving hi*hi + hi*lo + lo*hi exactly.
// Grid: (72 pixel-tiles, 4 batches, 5 M-tiles), 256 threads (8 warps).
// Warp tile 32x64 (2x4 wmma 16x16 frags). Smem: A[128][200]+B[128][200] bf16.
// ---------------------------------------------------------------------------
__global__ __launch_bounds__(256) void kG() {
    extern __shared__ __nv_bfloat16 sm[];
    __nv_bfloat16* sA = sm;                    // [128][KPAD]
    __nv_bfloat16* sB = sm + 128 * KPAD;       // [128][KPAD] (row n = K-major)

    const int tid = threadIdx.x;
    const int nx = blockIdx.x, b = blockIdx.y, mt = blockIdx.z;

    // Stage: 128 rows x 8 uint4 (=64 halves) per source, expand to 3 K-segments.
    for (int q = tid; q < 1024; q += 256) {
        int r = q >> 3, u = q & 7;
        uint4 wh = reinterpret_cast<const uint4*>(g_whi + (size_t)(mt * 128 + r) * Cc)[u];
        uint4 wl = reinterpret_cast<const uint4*>(g_wlo + (size_t)(mt * 128 + r) * Cc)[u];
        uint4* ra = reinterpret_cast<uint4*>(sA + r * KPAD);
        ra[u] = wh; ra[u + 8] = wh; ra[u + 16] = wl;
        size_t gidx = ((size_t)b * HW + nx * 128 + r) * Cc;
        uint4 xh = reinterpret_cast<const uint4*>(g_xhi + gidx)[u];
        uint4 xl = reinterpret_cast<const uint4*>(g_xlo + gidx)[u];
        uint4* rb = reinterpret_cast<uint4*>(sB + r * KPAD);
        rb[u] = xh; rb[u + 8] = xl; rb[u + 16] = xh;
    }
    __syncthreads();

    const int warp = tid >> 5;
    const int mw = warp >> 1;        // 0..3 -> rows mw*32
    const int nw = warp & 1;         // 0..1 -> cols nw*64
    const int m0 = mw * 32, n0 = nw * 64;

    wmma::fragment<wmma::accumulator, 16, 16, 16, float> acc[2][4];
#pragma unroll
    for (int i = 0; i < 2; i++)
#pragma unroll
        for (int j = 0; j < 4; j++) wmma::fill_fragment(acc[i][j], 0.f);

#pragma unroll 1
    for (int s = 0; s < 12; s++) {
        wmma::fragment<wmma::matrix_a, 16, 16, 16, __nv_bfloat16, wmma::row_major> af[2];
        wmma::fragment<wmma::matrix_b, 16, 16, 16, __nv_bfloat16, wmma::col_major> bf[4];
#pragma unroll
        for (int i = 0; i < 2; i++)
            wmma::load_matrix_sync(af[i], sA + (m0 + 16 * i) * KPAD + 16 * s, KPAD);
#pragma unroll
        for (int j = 0; j < 4; j++)
            wmma::load_matrix_sync(bf[j], sB + (n0 + 16 * j) * KPAD + 16 * s, KPAD);
#pragma unroll
        for (int i = 0; i < 2; i++)
#pragma unroll
            for (int j = 0; j < 4; j++)
                wmma::mma_sync(acc[i][j], af[i], bf[j], acc[i][j]);
    }

    const int jbase = mt * 128 + m0;
#pragma unroll
    for (int i = 0; i < 2; i++) {
        int jrow = jbase + 16 * i;
        if (jrow >= ON) continue;    // padded M rows
#pragma unroll
        for (int j = 0; j < 4; j++) {
            float* dst = g_Y + ((size_t)jrow * Bb + b) * HW + nx * 128 + n0 + 16 * j;
            wmma::store_matrix_sync(dst, acc[i][j], Bb * HW, wmma::mem_row_major);
        }
    }
}

// ---------------------------------------------------------------------------
// kB: pre-BN output = bias[o] + sum_n bilinear-blend(Y[o,n,b]) + BN partials.
// ---------------------------------------------------------------------------
struct alignas(16) Tap { int lo; int hi; float wl; float wr; };

__global__ __launch_bounds__(256) void kB(const float* __restrict__ frames,
                                          const float* __restrict__ bias,
                                          float* __restrict__ out) {
    __shared__ Tap SX[NT][Ww];
    __shared__ Tap SY[NT][Hh];
    __shared__ float rs[256], rq[256];

    const int o = blockIdx.z;
    const int b = blockIdx.y;

    for (int idx = threadIdx.x; idx < 2 * NT * 96; idx += 256) {
        int which = (idx >= NT * 96) ? 1 : 0;
        int r = idx - which * (NT * 96);
        int n = r / 96, t = r - n * 96;
        float d  = frames[o * (2 * NT) + which * NT + n];
        float pf = d + (float)t;
        float ff = floorf(pf);
        float lof = fminf(fmaxf(ff, 0.f), 95.f);
        float hif = fminf(fmaxf(ff + 1.f, 0.f), 95.f);
        float pc  = fminf(fmaxf(pf, 0.f), 95.f);
        Tap tp;
        tp.lo = (int)lof;
        tp.hi = (int)hif;
        tp.wl = 1.f + lof - pc;
        tp.wr = 1.f - hif + pc;
        if (which == 0) SX[n][t] = tp; else SY[n][t] = tp;
    }
    __syncthreads();

    const int p = blockIdx.x * 256 + threadIdx.x;
    const int h = p / Ww, w = p - h * Ww;
    const float* Ybase = g_Y + ((size_t)(o * NT) * Bb + b) * HW;

    float acc = 0.f;
#pragma unroll
    for (int n = 0; n < NT; n++) {
        Tap tx = SX[n][w];
        Tap ty = SY[n][h];
        const float* Yp = Ybase + (size_t)n * (Bb * HW);
        const float* rT = Yp + ty.lo * Ww;
        const float* rB = Yp + ty.hi * Ww;
        float vT = tx.wl * rT[tx.lo] + tx.wr * rT[tx.hi];
        float vB = tx.wl * rB[tx.lo] + tx.wr * rB[tx.hi];
        acc += ty.wl * vT + ty.wr * vB;
    }
    float v = acc + bias[o];
    out[(size_t)(b * Oo + o) * HW + p] = v;

    rs[threadIdx.x] = v;
    rq[threadIdx.x] = v * v;
    __syncthreads();
    for (int st = 128; st > 0; st >>= 1) {
        if (threadIdx.x < st) {
            rs[threadIdx.x] += rs[threadIdx.x + st];
            rq[threadIdx.x] += rq[threadIdx.x + st];
        }
        __syncthreads();
    }
    if (threadIdx.x == 0) {
        int slot = (o * Bb + b) * NBX + blockIdx.x;
        g_psum[slot] = rs[0];
        g_psq [slot] = rq[0];
    }
}

// ---------------------------------------------------------------------------
// kC1: reduce 144 partials per channel -> scale/shift.
// ---------------------------------------------------------------------------
__global__ __launch_bounds__(256) void kC1(const float* __restrict__ gamma,
                                           const float* __restrict__ beta) {
    const int o = blockIdx.x;
    const int P = Bb * NBX;
    float s = 0.f, s2 = 0.f;
    if (threadIdx.x < P) {
        s  = g_psum[o * P + threadIdx.x];
        s2 = g_psq [o * P + threadIdx.x];
    }
    __shared__ float rs[256], rq[256];
    rs[threadIdx.x] = s;
    rq[threadIdx.x] = s2;
    __syncthreads();
    for (int st = 128; st > 0; st >>= 1) {
        if (threadIdx.x < st) {
            rs[threadIdx.x] += rs[threadIdx.x + st];
            rq[threadIdx.x] += rq[threadIdx.x + st];
        }
        __syncthreads();
    }
    if (threadIdx.x == 0) {
        const float inv = 1.f / (float)(Bb * HW);
        float mean = rs[0] * inv;
        float var  = rq[0] * inv - mean * mean;
        float rstd = rsqrtf(var + 1e-5f);
        float sc = gamma[o] * rstd;
        g_scale[o] = sc;
        g_shift[o] = beta[o] - mean * sc;
    }
}

// ---------------------------------------------------------------------------
// kC2: in-place normalize + ReLU, float4.
// ---------------------------------------------------------------------------
__global__ __launch_bounds__(256) void kC2(float4* __restrict__ out) {
    const int idx = blockIdx.x * 256 + threadIdx.x;
    const int o = (idx / (HW / 4)) & 63;
    float sc = g_scale[o], sh = g_shift[o];
    float4 v = out[idx];
    v.x = fmaxf(fmaf(v.x, sc, sh), 0.f);
    v.y = fmaxf(fmaf(v.y, sc, sh), 0.f);
    v.z = fmaxf(fmaf(v.z, sc, sh), 0.f);
    v.w = fmaxf(fmaf(v.w, sc, sh), 0.f);
    out[idx] = v;
}

extern "C" void kernel_launch(void* const* d_in, const int* in_sizes, int n_in,
                              void* d_out, int out_size) {
    const float* x      = (const float*)d_in[0];
    const float* frames = (const float*)d_in[1];
    const float* cw     = (const float*)d_in[2];
    const float* cb     = (const float*)d_in[3];
    const float* gamma  = (const float*)d_in[4];
    const float* beta   = (const float*)d_in[5];
    float* out = (float*)d_out;

    const int SMEM_KG = 2 * 128 * KPAD * (int)sizeof(__nv_bfloat16);   // 102400 B
    cudaFuncSetAttribute(kG, cudaFuncAttributeMaxDynamicSharedMemorySize, SMEM_KG);

    kPW<<<(MPAD * Cc + 255) / 256, 256>>>(cw);
    kPX<<<(Bb * HW) / 256, 256>>>(x);
    kG<<<dim3(HW / 128, Bb, MPAD / 128), 256, SMEM_KG>>>();
    kB<<<dim3(HW / 256, Bb, Oo), 256>>>(frames, cb, out);
    kC1<<<Oo, 256>>>(gamma, beta);
    kC2<<<(Bb * Oo * HW) / 1024, 256>>>((float4*)out);
}

// round 12
// speedup vs baseline: 1.4136x; 1.0317x over previous
#include <cuda_runtime.h>
#include <cuda_bf16.h>
#include <mma.h>
#include <cstdint>

using namespace nvcuda;

#define Hh 96
#define Ww 96
#define HW 9216
#define Cc 64
#define Oo 64
#define Bb 4
#define NT 9            // taps per frame
#define ON 576          // Oo*NT = valid GEMM rows
#define MPAD 640        // padded to 5 tiles of 128
#define NBX 4           // kB blocks per (b,o) image
#define KPAD 200        // smem row stride in bf16

// Scratch
__device__ float g_Y[(size_t)ON * Bb * HW];                          // 85 MB
__device__ __align__(16) __nv_bfloat16 g_whi[MPAD * Cc];
__device__ __align__(16) __nv_bfloat16 g_wlo[MPAD * Cc];
__device__ __align__(16) __nv_bfloat16 g_xhi[(size_t)Bb * HW * Cc];
__device__ __align__(16) __nv_bfloat16 g_xlo[(size_t)Bb * HW * Cc];
__device__ float g_scale[Oo];
__device__ float g_shift[Oo];
__device__ float g_psum[Oo * Bb * NBX];
__device__ float g_psq [Oo * Bb * NBX];

// ---------------------------------------------------------------------------
// kPW: split conv weights into bf16 hi/lo, layout Wpad[j][c], j = o*9+n, pad 0.
// ---------------------------------------------------------------------------
__global__ __launch_bounds__(256) void kPW(const float* __restrict__ cw) {
    int idx = blockIdx.x * 256 + threadIdx.x;
    if (idx >= MPAD * Cc) return;
    int j = idx >> 6, c = idx & 63;
    float v = 0.f;
    if (j < ON) {
        int o = j / 9, n = j - o * 9;
        v = cw[(size_t)o * (Cc * NT) + c * NT + n];
    }
    __nv_bfloat16 hi = __float2bfloat16(v);
    __nv_bfloat16 lo = __float2bfloat16(v - __bfloat162float(hi));
    g_whi[idx] = hi;
    g_wlo[idx] = lo;
}

// ---------------------------------------------------------------------------
// kPX: transpose+split x -> xT[g][c] (g = b*HW+p), 128B K-major rows.
// ---------------------------------------------------------------------------
__global__ __launch_bounds__(256) void kPX(const float* __restrict__ x) {
    int g = blockIdx.x * 256 + threadIdx.x;
    int b = g / HW, p = g - b * HW;
    const float* xp = x + (size_t)b * Cc * HW + p;
    uint32_t hibuf[32], lobuf[32];
#pragma unroll
    for (int c2 = 0; c2 < 32; c2++) {
        float v0 = xp[(2 * c2) * HW];
        float v1 = xp[(2 * c2 + 1) * HW];
        __nv_bfloat16 h0 = __float2bfloat16(v0);
        __nv_bfloat16 h1 = __float2bfloat16(v1);
        __nv_bfloat16 l0 = __float2bfloat16(v0 - __bfloat162float(h0));
        __nv_bfloat16 l1 = __float2bfloat16(v1 - __bfloat162float(h1));
        __nv_bfloat162 hp = __halves2bfloat162(h0, h1);
        __nv_bfloat162 lp = __halves2bfloat162(l0, l1);
        hibuf[c2] = *reinterpret_cast<uint32_t*>(&hp);
        lobuf[c2] = *reinterpret_cast<uint32_t*>(&lp);
    }
    uint4* dh = reinterpret_cast<uint4*>(g_xhi + (size_t)g * Cc);
    uint4* dl = reinterpret_cast<uint4*>(g_xlo + (size_t)g * Cc);
#pragma unroll
    for (int q = 0; q < 8; q++) {
        dh[q] = make_uint4(hibuf[4*q], hibuf[4*q+1], hibuf[4*q+2], hibuf[4*q+3]);
        dl[q] = make_uint4(lobuf[4*q], lobuf[4*q+1], lobuf[4*q+2], lobuf[4*q+3]);
    }
}

// ---------------------------------------------------------------------------
// kG: WMMA bf16 split GEMM (unchanged from R11 pass).
// ---------------------------------------------------------------------------
__global__ __launch_bounds__(256) void kG() {
    extern __shared__ __nv_bfloat16 sm[];
    __nv_bfloat16* sA = sm;
    __nv_bfloat16* sB = sm + 128 * KPAD;

    const int tid = threadIdx.x;
    const int nx = blockIdx.x, b = blockIdx.y, mt = blockIdx.z;

    for (int q = tid; q < 1024; q += 256) {
        int r = q >> 3, u = q & 7;
        uint4 wh = reinterpret_cast<const uint4*>(g_whi + (size_t)(mt * 128 + r) * Cc)[u];
        uint4 wl = reinterpret_cast<const uint4*>(g_wlo + (size_t)(mt * 128 + r) * Cc)[u];
        uint4* ra = reinterpret_cast<uint4*>(sA + r * KPAD);
        ra[u] = wh; ra[u + 8] = wh; ra[u + 16] = wl;
        size_t gidx = ((size_t)b * HW + nx * 128 + r) * Cc;
        uint4 xh = reinterpret_cast<const uint4*>(g_xhi + gidx)[u];
        uint4 xl = reinterpret_cast<const uint4*>(g_xlo + gidx)[u];
        uint4* rb = reinterpret_cast<uint4*>(sB + r * KPAD);
        rb[u] = xh; rb[u + 8] = xl; rb[u + 16] = xh;
    }
    __syncthreads();

    const int warp = tid >> 5;
    const int mw = warp >> 1, nw = warp & 1;
    const int m0 = mw * 32, n0 = nw * 64;

    wmma::fragment<wmma::accumulator, 16, 16, 16, float> acc[2][4];
#pragma unroll
    for (int i = 0; i < 2; i++)
#pragma unroll
        for (int j = 0; j < 4; j++) wmma::fill_fragment(acc[i][j], 0.f);

#pragma unroll 1
    for (int s = 0; s < 12; s++) {
        wmma::fragment<wmma::matrix_a, 16, 16, 16, __nv_bfloat16, wmma::row_major> af[2];
        wmma::fragment<wmma::matrix_b, 16, 16, 16, __nv_bfloat16, wmma::col_major> bf[4];
#pragma unroll
        for (int i = 0; i < 2; i++)
            wmma::load_matrix_sync(af[i], sA + (m0 + 16 * i) * KPAD + 16 * s, KPAD);
#pragma unroll
        for (int j = 0; j < 4; j++)
            wmma::load_matrix_sync(bf[j], sB + (n0 + 16 * j) * KPAD + 16 * s, KPAD);
#pragma unroll
        for (int i = 0; i < 2; i++)
#pragma unroll
            for (int j = 0; j < 4; j++)
                wmma::mma_sync(acc[i][j], af[i], bf[j], acc[i][j]);
    }

    const int jbase = mt * 128 + m0;
#pragma unroll
    for (int i = 0; i < 2; i++) {
        int jrow = jbase + 16 * i;
        if (jrow >= ON) continue;
#pragma unroll
        for (int j = 0; j < 4; j++) {
            float* dst = g_Y + ((size_t)jrow * Bb + b) * HW + nx * 128 + n0 + 16 * j;
            wmma::store_matrix_sync(dst, acc[i][j], Bb * HW, wmma::mem_row_major);
        }
    }
}

// ---------------------------------------------------------------------------
// kB v2: gather + bias + BN partials.
// Block = 288 threads (3 rows x 96 cols), 8 px/thread -> 24 rows per block.
// Grid: (4 row-groups, B, O). Taps as premultiplied byte offsets; SY folds the
// plane stride so inner loop is IADD+LDG only. SY loads are warp-broadcast
// (uniform row per warp since 96 = 3*32); SX loaded once per 8 px.
// ---------------------------------------------------------------------------
struct alignas(16) TapX { int lo; int hi; float wl; float wr; };   // byte offs in row
struct alignas(16) TapY { int rlo; int rhi; float wl; float wr; }; // plane+row byte offs

__global__ __launch_bounds__(288) void kB(const float* __restrict__ frames,
                                          const float* __restrict__ bias,
                                          float* __restrict__ out) {
    __shared__ TapX SX[NT][Ww];
    __shared__ TapY SY[NT][Hh];
    __shared__ float ws[9], wq[9];

    const int o = blockIdx.z;
    const int b = blockIdx.y;
    const int tid = threadIdx.x;

    // Tap tables: 864 X-entries + 864 Y-entries.
    for (int idx = tid; idx < 2 * NT * 96; idx += 288) {
        int which = (idx >= NT * 96) ? 1 : 0;
        int r = idx - which * (NT * 96);
        int n = r / 96, t = r - n * 96;
        float d  = frames[o * (2 * NT) + which * NT + n];
        float pf = d + (float)t;
        float ff = floorf(pf);
        float lof = fminf(fmaxf(ff, 0.f), 95.f);
        float hif = fminf(fmaxf(ff + 1.f, 0.f), 95.f);
        float pc  = fminf(fmaxf(pf, 0.f), 95.f);
        float wl = 1.f + lof - pc;
        float wr = 1.f - hif + pc;
        if (which == 0) {
            TapX tp; tp.lo = (int)lof * 4; tp.hi = (int)hif * 4; tp.wl = wl; tp.wr = wr;
            SX[n][t] = tp;
        } else {
            TapY tp;
            int base = n * (Bb * HW) * 4;
            tp.rlo = base + (int)lof * (Ww * 4);
            tp.rhi = base + (int)hif * (Ww * 4);
            tp.wl = wl; tp.wr = wr;
            SY[n][t] = tp;
        }
    }
    __syncthreads();

    const int w  = tid % 96;
    const int rr = tid / 96;                 // 0..2
    const int r0 = blockIdx.x * 24;          // 24 rows per block
    const char* Yb = (const char*)(g_Y + ((size_t)(o * NT) * Bb + b) * HW);

    float acc[8];
#pragma unroll
    for (int k = 0; k < 8; k++) acc[k] = 0.f;

#pragma unroll
    for (int n = 0; n < NT; n++) {
        TapX tx = SX[n][w];
#pragma unroll
        for (int k = 0; k < 8; k++) {
            TapY ty = SY[n][r0 + rr + 3 * k];
            float LT = *(const float*)(Yb + (unsigned)(ty.rlo + tx.lo));
            float RT = *(const float*)(Yb + (unsigned)(ty.rlo + tx.hi));
            float LB = *(const float*)(Yb + (unsigned)(ty.rhi + tx.lo));
            float RB = *(const float*)(Yb + (unsigned)(ty.rhi + tx.hi));
            float vT = tx.wl * LT + tx.wr * RT;
            float vB = tx.wl * LB + tx.wr * RB;
            acc[k] += ty.wl * vT + ty.wr * vB;
        }
    }

    const float bo = bias[o];
    float* outp = out + (size_t)(b * Oo + o) * HW;
    float s = 0.f, s2 = 0.f;
#pragma unroll
    for (int k = 0; k < 8; k++) {
        float v = acc[k] + bo;
        outp[(r0 + rr + 3 * k) * Ww + w] = v;
        s += v;
        s2 += v * v;
    }

    // warp reduce, then 9 warp partials.
#pragma unroll
    for (int off = 16; off > 0; off >>= 1) {
        s  += __shfl_down_sync(0xFFFFFFFFu, s,  off);
        s2 += __shfl_down_sync(0xFFFFFFFFu, s2, off);
    }
    if ((tid & 31) == 0) { ws[tid >> 5] = s; wq[tid >> 5] = s2; }
    __syncthreads();
    if (tid == 0) {
        float S = 0.f, Q = 0.f;
#pragma unroll
        for (int i = 0; i < 9; i++) { S += ws[i]; Q += wq[i]; }
        int slot = (o * Bb + b) * NBX + blockIdx.x;
        g_psum[slot] = S;
        g_psq [slot] = Q;
    }
}

// ---------------------------------------------------------------------------
// kC1: reduce 16 partials per channel -> scale/shift.
// ---------------------------------------------------------------------------
__global__ __launch_bounds__(32) void kC1(const float* __restrict__ gamma,
                                          const float* __restrict__ beta) {
    const int o = blockIdx.x;
    const int P = Bb * NBX;   // 16
    const int t = threadIdx.x;
    float s = 0.f, s2 = 0.f;
    if (t < P) {
        s  = g_psum[o * P + t];
        s2 = g_psq [o * P + t];
    }
#pragma unroll
    for (int off = 16; off > 0; off >>= 1) {
        s  += __shfl_down_sync(0xFFFFFFFFu, s,  off);
        s2 += __shfl_down_sync(0xFFFFFFFFu, s2, off);
    }
    if (t == 0) {
        const float inv = 1.f / (float)(Bb * HW);
        float mean = s * inv;
        float var  = s2 * inv - mean * mean;
        float rstd = rsqrtf(var + 1e-5f);
        float sc = gamma[o] * rstd;
        g_scale[o] = sc;
        g_shift[o] = beta[o] - mean * sc;
    }
}

// ---------------------------------------------------------------------------
// kC2: in-place normalize + ReLU, float4.
// ---------------------------------------------------------------------------
__global__ __launch_bounds__(256) void kC2(float4* __restrict__ out) {
    const int idx = blockIdx.x * 256 + threadIdx.x;
    const int o = (idx / (HW / 4)) & 63;
    float sc = g_scale[o], sh = g_shift[o];
    float4 v = out[idx];
    v.x = fmaxf(fmaf(v.x, sc, sh), 0.f);
    v.y = fmaxf(fmaf(v.y, sc, sh), 0.f);
    v.z = fmaxf(fmaf(v.z, sc, sh), 0.f);
    v.w = fmaxf(fmaf(v.w, sc, sh), 0.f);
    out[idx] = v;
}

extern "C" void kernel_launch(void* const* d_in, const int* in_sizes, int n_in,
                              void* d_out, int out_size) {
    const float* x      = (const float*)d_in[0];
    const float* frames = (const float*)d_in[1];
    const float* cw     = (const float*)d_in[2];
    const float* cb     = (const float*)d_in[3];
    const float* gamma  = (const float*)d_in[4];
    const float* beta   = (const float*)d_in[5];
    float* out = (float*)d_out;

    const int SMEM_KG = 2 * 128 * KPAD * (int)sizeof(__nv_bfloat16);   // 102400 B
    cudaFuncSetAttribute(kG, cudaFuncAttributeMaxDynamicSharedMemorySize, SMEM_KG);

    kPW<<<(MPAD * Cc + 255) / 256, 256>>>(cw);
    kPX<<<(Bb * HW) / 256, 256>>>(x);
    kG<<<dim3(HW / 128, Bb, MPAD / 128), 256, SMEM_KG>>>();
    kB<<<dim3(NBX, Bb, Oo), 288>>>(frames, cb, out);
    kC1<<<Oo, 32>>>(gamma, beta);
    kC2<<<(Bb * Oo * HW) / 1024, 256>>>((float4*)out);
}

// round 16
// speedup vs baseline: 1.7021x; 1.2041x over previous
#include <cuda_runtime.h>
#include <cuda_bf16.h>
#include <mma.h>
#include <cstdint>

using namespace nvcuda;

#define Hh 96
#define Ww 96
#define HW 9216
#define Cc 64
#define Oo 64
#define Bb 4
#define NT 9            // taps per frame
#define ON 576          // Oo*NT = valid GEMM rows
#define MPAD 640        // padded to 5 tiles of 128
#define NBX 8           // kB blocks per (b,o) image (12 rows each)
#define KPAD 200        // smem row stride in bf16

// Scratch
__device__ float g_Y[(size_t)ON * Bb * HW];                          // 85 MB
__device__ __align__(16) __nv_bfloat16 g_whi[MPAD * Cc];
__device__ __align__(16) __nv_bfloat16 g_wlo[MPAD * Cc];
__device__ __align__(16) __nv_bfloat16 g_xhi[(size_t)Bb * HW * Cc];
__device__ __align__(16) __nv_bfloat16 g_xlo[(size_t)Bb * HW * Cc];
__device__ float g_scale[Oo];
__device__ float g_shift[Oo];
__device__ float g_psum[Oo * Bb * NBX];
__device__ float g_psq [Oo * Bb * NBX];

// ---------------------------------------------------------------------------
// kPW: split conv weights into bf16 hi/lo, layout Wpad[j][c], j = o*9+n, pad 0.
// ---------------------------------------------------------------------------
__global__ __launch_bounds__(256) void kPW(const float* __restrict__ cw) {
    int idx = blockIdx.x * 256 + threadIdx.x;
    if (idx >= MPAD * Cc) return;
    int j = idx >> 6, c = idx & 63;
    float v = 0.f;
    if (j < ON) {
        int o = j / 9, n = j - o * 9;
        v = cw[(size_t)o * (Cc * NT) + c * NT + n];
    }
    __nv_bfloat16 hi = __float2bfloat16(v);
    __nv_bfloat16 lo = __float2bfloat16(v - __bfloat162float(hi));
    g_whi[idx] = hi;
    g_wlo[idx] = lo;
}

// ---------------------------------------------------------------------------
// kPX: transpose+split x -> xT[g][c] (g = b*HW+p), 128B K-major rows.
// ---------------------------------------------------------------------------
__global__ __launch_bounds__(256) void kPX(const float* __restrict__ x) {
    int g = blockIdx.x * 256 + threadIdx.x;
    int b = g / HW, p = g - b * HW;
    const float* xp = x + (size_t)b * Cc * HW + p;
    uint32_t hibuf[32], lobuf[32];
#pragma unroll
    for (int c2 = 0; c2 < 32; c2++) {
        float v0 = xp[(2 * c2) * HW];
        float v1 = xp[(2 * c2 + 1) * HW];
        __nv_bfloat16 h0 = __float2bfloat16(v0);
        __nv_bfloat16 h1 = __float2bfloat16(v1);
        __nv_bfloat16 l0 = __float2bfloat16(v0 - __bfloat162float(h0));
        __nv_bfloat16 l1 = __float2bfloat16(v1 - __bfloat162float(h1));
        __nv_bfloat162 hp = __halves2bfloat162(h0, h1);
        __nv_bfloat162 lp = __halves2bfloat162(l0, l1);
        hibuf[c2] = *reinterpret_cast<uint32_t*>(&hp);
        lobuf[c2] = *reinterpret_cast<uint32_t*>(&lp);
    }
    uint4* dh = reinterpret_cast<uint4*>(g_xhi + (size_t)g * Cc);
    uint4* dl = reinterpret_cast<uint4*>(g_xlo + (size_t)g * Cc);
#pragma unroll
    for (int q = 0; q < 8; q++) {
        dh[q] = make_uint4(hibuf[4*q], hibuf[4*q+1], hibuf[4*q+2], hibuf[4*q+3]);
        dl[q] = make_uint4(lobuf[4*q], lobuf[4*q+1], lobuf[4*q+2], lobuf[4*q+3]);
    }
}

// ---------------------------------------------------------------------------
// kG: WMMA bf16 split GEMM (unchanged from R11 pass).
// ---------------------------------------------------------------------------
__global__ __launch_bounds__(256) void kG() {
    extern __shared__ __nv_bfloat16 sm[];
    __nv_bfloat16* sA = sm;
    __nv_bfloat16* sB = sm + 128 * KPAD;

    const int tid = threadIdx.x;
    const int nx = blockIdx.x, b = blockIdx.y, mt = blockIdx.z;

    for (int q = tid; q < 1024; q += 256) {
        int r = q >> 3, u = q & 7;
        uint4 wh = reinterpret_cast<const uint4*>(g_whi + (size_t)(mt * 128 + r) * Cc)[u];
        uint4 wl = reinterpret_cast<const uint4*>(g_wlo + (size_t)(mt * 128 + r) * Cc)[u];
        uint4* ra = reinterpret_cast<uint4*>(sA + r * KPAD);
        ra[u] = wh; ra[u + 8] = wh; ra[u + 16] = wl;
        size_t gidx = ((size_t)b * HW + nx * 128 + r) * Cc;
        uint4 xh = reinterpret_cast<const uint4*>(g_xhi + gidx)[u];
        uint4 xl = reinterpret_cast<const uint4*>(g_xlo + gidx)[u];
        uint4* rb = reinterpret_cast<uint4*>(sB + r * KPAD);
        rb[u] = xh; rb[u + 8] = xl; rb[u + 16] = xh;
    }
    __syncthreads();

    const int warp = tid >> 5;
    const int mw = warp >> 1, nw = warp & 1;
    const int m0 = mw * 32, n0 = nw * 64;

    wmma::fragment<wmma::accumulator, 16, 16, 16, float> acc[2][4];
#pragma unroll
    for (int i = 0; i < 2; i++)
#pragma unroll
        for (int j = 0; j < 4; j++) wmma::fill_fragment(acc[i][j], 0.f);

#pragma unroll 1
    for (int s = 0; s < 12; s++) {
        wmma::fragment<wmma::matrix_a, 16, 16, 16, __nv_bfloat16, wmma::row_major> af[2];
        wmma::fragment<wmma::matrix_b, 16, 16, 16, __nv_bfloat16, wmma::col_major> bf[4];
#pragma unroll
        for (int i = 0; i < 2; i++)
            wmma::load_matrix_sync(af[i], sA + (m0 + 16 * i) * KPAD + 16 * s, KPAD);
#pragma unroll
        for (int j = 0; j < 4; j++)
            wmma::load_matrix_sync(bf[j], sB + (n0 + 16 * j) * KPAD + 16 * s, KPAD);
#pragma unroll
        for (int i = 0; i < 2; i++)
#pragma unroll
            for (int j = 0; j < 4; j++)
                wmma::mma_sync(acc[i][j], af[i], bf[j], acc[i][j]);
    }

    const int jbase = mt * 128 + m0;
#pragma unroll
    for (int i = 0; i < 2; i++) {
        int jrow = jbase + 16 * i;
        if (jrow >= ON) continue;
#pragma unroll
        for (int j = 0; j < 4; j++) {
            float* dst = g_Y + ((size_t)jrow * Bb + b) * HW + nx * 128 + n0 + 16 * j;
            wmma::store_matrix_sync(dst, acc[i][j], Bb * HW, wmma::mem_row_major);
        }
    }
}

// ---------------------------------------------------------------------------
// kB v3: gather + bias + BN partials, exploiting rhi(h) == rlo(h+1).
// Block = 288 threads (3 warp-rows x 96 cols); each thread does 4 consecutive
// rows of one column -> block covers 12 rows. Grid: (8, B, O).
// ---------------------------------------------------------------------------
struct alignas(16) TapX { int lo; int hi; float wl; float wr; };   // col byte offs
struct alignas(16) TapY { int rlo; int rhi; float wl; float wr; }; // plane+row byte offs

__global__ __launch_bounds__(288) void kB(const float* __restrict__ frames,
                                          const float* __restrict__ bias,
                                          float* __restrict__ out) {
    __shared__ TapX SX[NT][Ww];
    __shared__ TapY SY[NT][12];
    __shared__ float ws[9], wq[9];

    const int o = blockIdx.z;
    const int b = blockIdx.y;
    const int tid = threadIdx.x;
    const int r0 = blockIdx.x * 12;

    // Tap tables: 864 X-entries + 108 Y-entries (block's 12 rows).
    for (int idx = tid; idx < NT * 96 + NT * 12; idx += 288) {
        int which = (idx >= NT * 96) ? 1 : 0;
        int r = idx - which * (NT * 96);
        int n, t;
        if (!which) { n = r / 96; t = r - n * 96; }
        else        { n = r / 12; t = r0 + (r - n * 12); }
        float d  = frames[o * (2 * NT) + which * NT + n];
        float pf = d + (float)t;
        float ff = floorf(pf);
        float lof = fminf(fmaxf(ff, 0.f), 95.f);
        float hif = fminf(fmaxf(ff + 1.f, 0.f), 95.f);
        float pc  = fminf(fmaxf(pf, 0.f), 95.f);
        float wl = 1.f + lof - pc;
        float wr = 1.f - hif + pc;
        if (!which) {
            TapX tp; tp.lo = (int)lof * 4; tp.hi = (int)hif * 4; tp.wl = wl; tp.wr = wr;
            SX[n][t] = tp;
        } else {
            TapY tp;
            int base = n * (Bb * HW) * 4;
            tp.rlo = base + (int)lof * (Ww * 4);
            tp.rhi = base + (int)hif * (Ww * 4);
            tp.wl = wl; tp.wr = wr;
            SY[n][r - n * 12] = tp;
        }
    }
    __syncthreads();

    const int w  = tid % 96;
    const int rr = tid / 96;                 // 0..2 -> rows r0+rr*4 .. +3
    const int hb = rr * 4;                   // local row base in SY
    const char* Yb = (const char*)(g_Y + ((size_t)(o * NT) * Bb + b) * HW);

    float acc[4] = {0.f, 0.f, 0.f, 0.f};

#pragma unroll
    for (int n = 0; n < NT; n++) {
        TapX tx = SX[n][w];
        TapY t0 = SY[n][hb + 0];
        TapY t1 = SY[n][hb + 1];
        TapY t2 = SY[n][hb + 2];
        TapY t3 = SY[n][hb + 3];
        // 5 distinct Y rows: rlo of each + rhi of last (rhi(h) == rlo(h+1)).
        int R0 = t0.rlo, R1 = t1.rlo, R2 = t2.rlo, R3 = t3.rlo, R4 = t3.rhi;
        float r0v = tx.wl * *(const float*)(Yb + (unsigned)(R0 + tx.lo))
                  + tx.wr * *(const float*)(Yb + (unsigned)(R0 + tx.hi));
        float r1v = tx.wl * *(const float*)(Yb + (unsigned)(R1 + tx.lo))
                  + tx.wr * *(const float*)(Yb + (unsigned)(R1 + tx.hi));
        float r2v = tx.wl * *(const float*)(Yb + (unsigned)(R2 + tx.lo))
                  + tx.wr * *(const float*)(Yb + (unsigned)(R2 + tx.hi));
        float r3v = tx.wl * *(const float*)(Yb + (unsigned)(R3 + tx.lo))
                  + tx.wr * *(const float*)(Yb + (unsigned)(R3 + tx.hi));
        float r4v = tx.wl * *(const float*)(Yb + (unsigned)(R4 + tx.lo))
                  + tx.wr * *(const float*)(Yb + (unsigned)(R4 + tx.hi));
        acc[0] += t0.wl * r0v + t0.wr * r1v;
        acc[1] += t1.wl * r1v + t1.wr * r2v;
        acc[2] += t2.wl * r2v + t2.wr * r3v;
        acc[3] += t3.wl * r3v + t3.wr * r4v;
    }

    const float bo = bias[o];
    float* outp = out + (size_t)(b * Oo + o) * HW + (r0 + rr * 4) * Ww + w;
    float s = 0.f, s2 = 0.f;
#pragma unroll
    for (int k = 0; k < 4; k++) {
        float v = acc[k] + bo;
        outp[k * Ww] = v;
        s += v;
        s2 += v * v;
    }

#pragma unroll
    for (int off = 16; off > 0; off >>= 1) {
        s  += __shfl_down_sync(0xFFFFFFFFu, s,  off);
        s2 += __shfl_down_sync(0xFFFFFFFFu, s2, off);
    }
    if ((tid & 31) == 0) { ws[tid >> 5] = s; wq[tid >> 5] = s2; }
    __syncthreads();
    if (tid == 0) {
        float S = 0.f, Q = 0.f;
#pragma unroll
        for (int i = 0; i < 9; i++) { S += ws[i]; Q += wq[i]; }
        int slot = (o * Bb + b) * NBX + blockIdx.x;
        g_psum[slot] = S;
        g_psq [slot] = Q;
    }
}

// ---------------------------------------------------------------------------
// kC1: reduce 32 partials per channel -> scale/shift.
// ---------------------------------------------------------------------------
__global__ __launch_bounds__(32) void kC1(const float* __restrict__ gamma,
                                          const float* __restrict__ beta) {
    const int o = blockIdx.x;
    const int P = Bb * NBX;   // 32
    const int t = threadIdx.x;
    float s = 0.f, s2 = 0.f;
    if (t < P) {
        s  = g_psum[o * P + t];
        s2 = g_psq [o * P + t];
    }
#pragma unroll
    for (int off = 16; off > 0; off >>= 1) {
        s  += __shfl_down_sync(0xFFFFFFFFu, s,  off);
        s2 += __shfl_down_sync(0xFFFFFFFFu, s2, off);
    }
    if (t == 0) {
        const float inv = 1.f / (float)(Bb * HW);
        float mean = s * inv;
        float var  = s2 * inv - mean * mean;
        float rstd = rsqrtf(var + 1e-5f);
        float sc = gamma[o] * rstd;
        g_scale[o] = sc;
        g_shift[o] = beta[o] - mean * sc;
    }
}

// ---------------------------------------------------------------------------
// kC2: in-place normalize + ReLU, float4.
// ---------------------------------------------------------------------------
__global__ __launch_bounds__(256) void kC2(float4* __restrict__ out) {
    const int idx = blockIdx.x * 256 + threadIdx.x;
    const int o = (idx / (HW / 4)) & 63;
    float sc = g_scale[o], sh = g_shift[o];
    float4 v = out[idx];
    v.x = fmaxf(fmaf(v.x, sc, sh), 0.f);
    v.y = fmaxf(fmaf(v.y, sc, sh), 0.f);
    v.z = fmaxf(fmaf(v.z, sc, sh), 0.f);
    v.w = fmaxf(fmaf(v.w, sc, sh), 0.f);
    out[idx] = v;
}

extern "C" void kernel_launch(void* const* d_in, const int* in_sizes, int n_in,
                              void* d_out, int out_size) {
    const float* x      = (const float*)d_in[0];
    const float* frames = (const float*)d_in[1];
    const float* cw     = (const float*)d_in[2];
    const float* cb     = (const float*)d_in[3];
    const float* gamma  = (const float*)d_in[4];
    const float* beta   = (const float*)d_in[5];
    float* out = (float*)d_out;

    const int SMEM_KG = 2 * 128 * KPAD * (int)sizeof(__nv_bfloat16);   // 102400 B
    cudaFuncSetAttribute(kG, cudaFuncAttributeMaxDynamicSharedMemorySize, SMEM_KG);

    kPW<<<(MPAD * Cc + 255) / 256, 256>>>(cw);
    kPX<<<(Bb * HW) / 256, 256>>>(x);
    kG<<<dim3(HW / 128, Bb, MPAD / 128), 256, SMEM_KG>>>();
    kB<<<dim3(NBX, Bb, Oo), 288>>>(frames, cb, out);
    kC1<<<Oo, 32>>>(gamma, beta);
    kC2<<<(Bb * Oo * HW) / 1024, 256>>>((float4*)out);
}